// round 4
// baseline (speedup 1.0000x reference)
#include <cuda_runtime.h>

#define Bc 16
#define Sc 512
#define Dc 768
#define Lc 20
#define INNERc 64
#define NPROJ 168          // 128 (w1) + 40 (w2)
#define ROWS (Bc*Sc)       // 8192
#define NEGV 1000000000000.0f
#define NTOT (Bc*Lc*Sc*Sc) // 83886080

// scratch (no allocation allowed -> __device__ globals)
__device__ float  g_q[ROWS * INNERc];     // rope'd q
__device__ float  g_k[ROWS * INNERc];     // rope'd k
__device__ float  g_d[ROWS * 40];         // (x@w2+b2)/2
__device__ float2 g_trig[Sc * 32];        // (sin, cos) per (s, pair i)

// ---------------------------------------------------------------------------
// Kernel 0: trig table. Only 16384 unique (s, i) pairs exist; do the fp64
// work (freq + range reduction) once here. sinf/cosf on a reduced arg in
// [-pi, pi] stays accurate (~5e-7) even with --use_fast_math.
// ---------------------------------------------------------------------------
__global__ __launch_bounds__(256) void trig_kernel()
{
    int gid = blockIdx.x * 256 + threadIdx.x;   // Sc*32 = 16384
    int s = gid >> 5;
    int i = gid & 31;

    // freq = fp32(10000^(-2i/64)) — match reference's fp32 value
    float freq = (float)exp(-2.0 * (double)i / 64.0 * log(10000.0));
    float ang  = (float)s * freq;               // fp32 rounding as in reference

    const double TWO_PI = 6.283185307179586;
    double a = (double)ang;
    double r = a - TWO_PI * floor(a / TWO_PI);
    if (r > 3.141592653589793) r -= TWO_PI;
    float rf = (float)r;

    g_trig[gid] = make_float2(sinf(rf), cosf(rf));
}

// ---------------------------------------------------------------------------
// Kernel 1: projection GEMM + fused RoPE epilogue.
// 32 rows per block, 168 cols, K=768 in 32-chunks. After the mainloop the
// output tile is staged in the (dead) smem pool as ps[32][172] (stride % 4
// == 0 -> float4 reads aligned & conflict-free), then roped straight to
// g_q/g_k and copied (x0.5) to g_d. No g_proj round trip, no rope kernel.
// ---------------------------------------------------------------------------
#define PS_STRIDE 172
#define POOL_FLOATS (32*33 + 32*NPROJ)   // 6432 >= 32*172 = 5504

__global__ __launch_bounds__(256) void proj_rope_kernel(
    const float* __restrict__ x,
    const float* __restrict__ w1, const float* __restrict__ b1,
    const float* __restrict__ w2, const float* __restrict__ b2)
{
    __shared__ __align__(16) float pool[POOL_FLOATS];
    float (*xs)[33]        = (float(*)[33])pool;
    float (*ws)[NPROJ]     = (float(*)[NPROJ])(pool + 32 * 33);
    float (*ps)[PS_STRIDE] = (float(*)[PS_STRIDE])pool;   // aliases xs/ws

    const int t    = threadIdx.x;
    const int lane = t & 31;
    const int warp = t >> 5;
    const int row0 = blockIdx.x * 32;

    float acc[4][6];
#pragma unroll
    for (int i = 0; i < 4; i++)
#pragma unroll
        for (int c = 0; c < 6; c++) acc[i][c] = 0.f;

    for (int k0 = 0; k0 < Dc; k0 += 32) {
#pragma unroll
        for (int i = 0; i < 4; i++) {
            int f = t + i * 256;
            int r = f >> 5, kk = f & 31;
            xs[r][kk] = x[(row0 + r) * Dc + k0 + kk];
        }
#pragma unroll
        for (int i = 0; i < 16; i++) {
            int f = t + i * 256;
            int kk = f >> 7, n = f & 127;
            ws[kk][n] = w1[(k0 + kk) * 128 + n];
        }
#pragma unroll
        for (int i = 0; i < 5; i++) {
            int f = t + i * 256;
            if (f < 32 * 40) {
                int kk = f / 40, n = f % 40;
                ws[kk][128 + n] = w2[(k0 + kk) * 40 + n];
            }
        }
        __syncthreads();
#pragma unroll 8
        for (int kk = 0; kk < 32; kk++) {
            float xv[4];
#pragma unroll
            for (int i = 0; i < 4; i++) xv[i] = xs[warp * 4 + i][kk];
#pragma unroll
            for (int c = 0; c < 6; c++) {
                int col = lane + 32 * c;
                if (col < NPROJ) {
                    float wv = ws[kk][col];
#pragma unroll
                    for (int i = 0; i < 4; i++) acc[i][c] += xv[i] * wv;
                }
            }
        }
        __syncthreads();   // last iteration: also protects the ps aliasing below
    }

    // stage acc+bias into smem (tile layout [row][col])
#pragma unroll
    for (int c = 0; c < 6; c++) {
        int col = lane + 32 * c;
        if (col < NPROJ) {
            float bias = (col < 128) ? b1[col] : b2[col - 128];
#pragma unroll
            for (int i = 0; i < 4; i++)
                ps[warp * 4 + i][col] = acc[i][c] + bias;
        }
    }
    __syncthreads();

    // RoPE + split: 32 rows x 32 pairs = 1024 items, 4 per thread.
    // pair i: q = (out1[4i], out1[4i+2]), k = (out1[4i+1], out1[4i+3])
#pragma unroll
    for (int it = 0; it < 4; it++) {
        int f   = t + it * 256;
        int r   = f >> 5;          // 0..31
        int i   = f & 31;          // pair index
        int row = row0 + r;
        int s   = row & (Sc - 1);

        float2 tr = g_trig[(s << 5) | i];
        float sn = tr.x, cs = tr.y;

        float4 v = *(const float4*)&ps[r][4 * i];   // q0,k0,q1,k1
        *(float2*)&g_q[row * INNERc + 2 * i] =
            make_float2(v.x * cs - v.z * sn, v.z * cs + v.x * sn);
        *(float2*)&g_k[row * INNERc + 2 * i] =
            make_float2(v.y * cs - v.w * sn, v.w * cs + v.y * sn);
    }

    // dense channels: 32 rows x 40 = 1280 items, scaled by 0.5
#pragma unroll
    for (int it = 0; it < 5; it++) {
        int f = t + it * 256;
        int r = f / 40, j = f % 40;
        g_d[(row0 + r) * 40 + j] = ps[r][128 + j] * 0.5f;
    }
}

// ---------------------------------------------------------------------------
// Kernel 2: logit expansion + sigmoid.
// One block per (b, mt, nt) 64x64 tile. qk tile computed once in registers,
// reused across all L=20 layers.
// Thread (tx,ty): m = m0+ty+16i (i<4), n = n0+4*tx+j (j<4) -> all global
// stores are STG.128 with warps writing 256B contiguous segments.
// k tile and n-side dense bias are stored TRANSPOSED in smem so kv/dnv are
// conflict-free LDS.128 loads.
// ---------------------------------------------------------------------------
__global__ __launch_bounds__(256) void logits_kernel(
    const int* __restrict__ amask, float* __restrict__ out)
{
    __shared__ float qs[64][65];      // [m][d], broadcast reads
    __shared__ float kst[64][64];     // [d][n] transposed
    __shared__ float dms[64][21];     // [m][l] odd channels (2l+1)
    __shared__ float dnst[20][64];    // [l][n] even channels (2l), transposed
    __shared__ float maskM[64];
    __shared__ float maskN[64];

    const int t  = threadIdx.x;
    const int tx = t & 15;
    const int ty = t >> 4;
    const int nt = blockIdx.x, mt = blockIdx.y, b = blockIdx.z;
    const int m0 = mt * 64, n0 = nt * 64;

    {
        const float4* qg = (const float4*)(g_q + (b * Sc + m0) * INNERc);
        const float4* kg = (const float4*)(g_k + (b * Sc + n0) * INNERc);
#pragma unroll
        for (int i = 0; i < 4; i++) {
            int f = t + i * 256;            // 1024 float4s
            int r = f >> 4, d4 = f & 15;
            float4 v = qg[f];
            qs[r][d4 * 4 + 0] = v.x; qs[r][d4 * 4 + 1] = v.y;
            qs[r][d4 * 4 + 2] = v.z; qs[r][d4 * 4 + 3] = v.w;
            v = kg[f];
            kst[d4 * 4 + 0][r] = v.x; kst[d4 * 4 + 1][r] = v.y;
            kst[d4 * 4 + 2][r] = v.z; kst[d4 * 4 + 3][r] = v.w;
        }
    }
#pragma unroll
    for (int i = 0; i < 5; i++) {
        int f = t + i * 256;
        if (f < 64 * 20) {
            int r = f / 20, l = f % 20;
            dms[r][l]  = g_d[(b * Sc + m0 + r) * 40 + 2 * l + 1];
            dnst[l][r] = g_d[(b * Sc + n0 + r) * 40 + 2 * l];
        }
    }
    if (t < 64)            maskM[t]      = (float)amask[b * Sc + m0 + t];
    else if (t < 128)      maskN[t - 64] = (float)amask[b * Sc + n0 + (t - 64)];
    __syncthreads();

    float acc[4][4];
#pragma unroll
    for (int i = 0; i < 4; i++)
#pragma unroll
        for (int j = 0; j < 4; j++) acc[i][j] = 0.f;

#pragma unroll 16
    for (int d = 0; d < 64; d++) {
        float4 kv = *(const float4*)&kst[d][4 * tx];   // LDS.128, conflict-free
        float qv[4];
#pragma unroll
        for (int i = 0; i < 4; i++) qv[i] = qs[ty + 16 * i][d];  // broadcast
#pragma unroll
        for (int i = 0; i < 4; i++) {
            acc[i][0] += qv[i] * kv.x;
            acc[i][1] += qv[i] * kv.y;
            acc[i][2] += qv[i] * kv.z;
            acc[i][3] += qv[i] * kv.w;
        }
    }

    float mmv[4], negmi[4], mnv[4], negmj[4], cz[4][4];
#pragma unroll
    for (int j = 0; j < 4; j++) {
        mnv[j]   = maskN[4 * tx + j];
        negmj[j] = -NEGV * (1.0f - mnv[j]);
    }
#pragma unroll
    for (int i = 0; i < 4; i++) {
        mmv[i]   = maskM[ty + 16 * i];
        negmi[i] = -NEGV * (1.0f - mmv[i]);
#pragma unroll
        for (int j = 0; j < 4; j++) {
            acc[i][j] *= 0.125f;                 // 1/sqrt(64), exact
            int m = m0 + ty + 16 * i, n = n0 + 4 * tx + j;
            cz[i][j] = (m > n) ? -NEGV : 0.0f;
        }
    }

    const int SS    = Sc * Sc;
    const int pbase = b * Lc * SS + (m0 + ty) * Sc + n0 + 4 * tx;
    float* __restrict__ outP = out + NTOT;

    for (int l = 0; l < Lc; l++) {
        float4 dnv = *(const float4*)&dnst[l][4 * tx];  // LDS.128
        float dn[4] = {dnv.x, dnv.y, dnv.z, dnv.w};
        float dmv[4];
#pragma unroll
        for (int i = 0; i < 4; i++) dmv[i] = dms[ty + 16 * i][l];

        int lbase = pbase + l * SS;
#pragma unroll
        for (int i = 0; i < 4; i++) {
            float4 vlog, vprob;
            float* vl = &vlog.x;
            float* vp = &vprob.x;
#pragma unroll
            for (int j = 0; j < 4; j++) {
                // match reference op order: (qk/8 + dq_n) + dk_m
                float v = (acc[i][j] + dn[j]) + dmv[i];
                v = fmaf(v, mmv[i], negmi[i]);   // *m1 - NEG*(1-m1)
                v = fmaf(v, mnv[j], negmj[j]);   // *m2 - NEG*(1-m2)
                v = v + cz[i][j];                // - tril*NEG
                vl[j] = v;
                vp[j] = __fdividef(1.0f, 1.0f + __expf(-v));
            }
            int idx = lbase + i * 16 * Sc;       // multiple of 4 (n0+4tx)
            *(float4*)(out  + idx) = vlog;       // STG.128
            *(float4*)(outP + idx) = vprob;      // STG.128
        }
    }
}

// ---------------------------------------------------------------------------
extern "C" void kernel_launch(void* const* d_in, const int* in_sizes, int n_in,
                              void* d_out, int out_size)
{
    const float* x   = (const float*)d_in[0];
    const int*   am  = (const int*)  d_in[1];
    const float* w1  = (const float*)d_in[2];
    const float* b1  = (const float*)d_in[3];
    const float* w2  = (const float*)d_in[4];
    const float* b2  = (const float*)d_in[5];
    float* out = (float*)d_out;

    trig_kernel<<<Sc * 32 / 256, 256>>>();
    proj_rope_kernel<<<ROWS / 32, 256>>>(x, w1, b1, w2, b2);
    logits_kernel<<<dim3(Sc / 64, Sc / 64, Bc), 256>>>(am, out);
}